// round 10
// baseline (speedup 1.0000x reference)
#include <cuda_runtime.h>
#include <cstdint>

#define TT 16384
#define CC 1024
#define NROWS 128           // tail rows in stats table (window provably < 25)
#define N_ITERS 30
#define GRID 144            // <= 148 SMs -> one wave, safe software grid barrier
#define NTH 256

__device__ float g_uacc[CC];       // static zero; atomically accumulated; reset by block 0
__device__ float g_att[NROWS];
__device__ float g_av[NROWS];
__device__ int   g_barc[2 * 32];   // one cache line per phase; left 0 after launch

#define SCALE 3.125e-5f     // 0.001 / sqrt(1024)

__device__ __forceinline__ float neg_inf() { return __int_as_float(0xff800000); }

__device__ __forceinline__ void gbar_arrive(int ph) {
    __syncthreads();
    if (threadIdx.x == 0) {
        __threadfence();
        atomicAdd(&g_barc[ph << 5], 1);
    }
}
__device__ __forceinline__ void gbar_wait(int ph, int count) {
    if (threadIdx.x == 0) {
        while (*(volatile int*)&g_barc[ph << 5] < count) { }
        __threadfence();
    }
    __syncthreads();
}

__device__ __forceinline__ float wred_sum(float v) {
#pragma unroll
    for (int o = 16; o; o >>= 1) v += __shfl_xor_sync(0xffffffffu, v, o);
    return v;
}

__global__ void __launch_bounds__(NTH, 1)
k_all(const float* __restrict__ x, const float* __restrict__ W,
      const float* __restrict__ alpha, const float* __restrict__ beta,
      float* __restrict__ out)
{
    __shared__ float  sq[8];                   // this block's 8 q values
    __shared__ float  sbuf[CC];                // u (stage C / D fallback)
    __shared__ float  sS[NROWS + 1], sB[NROWS + 1], sY[NROWS + 1];
    __shared__ float  bu_tab[NROWS + 1];
    __shared__ float  tia[32];
    __shared__ float  red[8];
    __shared__ float  fm[8], fs[8], fb[8], fy[8];
    __shared__ float  smax, salpha, sbeta;

    const int b = blockIdx.x, t = threadIdx.x;
    const int lane = t & 31, wid = t >> 5;

    if (b == 0 && t == 0) { salpha = *alpha; sbeta = *beta; }

    // ===== STAGE A+B (blocks 0-127): q for 8 rows -> partial u -> atomic acc ===
    if (b < 128) {
        const int i0 = b << 3;
        const float* Wk = W + (size_t)CC * CC;

        // coalesced front-batch of this block's 8 full W_k rows
        float4 wk[8];
#pragma unroll
        for (int k = 0; k < 8; k++)
            wk[k] = ((const float4*)(Wk + (size_t)(i0 + k) * CC))[t];

        // q[i0+wid] = x_last . W_q[i0+wid]
        const float4* xl4 = (const float4*)(x + (size_t)(TT - 1) * CC);
        const float4* wr4 = (const float4*)(W + (size_t)(i0 + wid) * CC);
        float4 xa[8], wa[8];
#pragma unroll
        for (int c = 0; c < 8; c++) xa[c] = xl4[c * 32 + lane];
#pragma unroll
        for (int c = 0; c < 8; c++) wa[c] = wr4[c * 32 + lane];
        float s = 0.f;
#pragma unroll
        for (int c = 0; c < 8; c++)
            s += xa[c].x * wa[c].x + xa[c].y * wa[c].y + xa[c].z * wa[c].z + xa[c].w * wa[c].w;
        s = wred_sum(s);
        if (lane == 0) sq[wid] = s;
        __syncthreads();                        // also publishes salpha/sbeta (block 0)

        // partial u for all 1024 j (thread t owns floats 4t..4t+3) -> atomic acc
        float4 acc = make_float4(0.f, 0.f, 0.f, 0.f);
#pragma unroll
        for (int k = 0; k < 8; k++) {
            float q = sq[k];
            acc.x += q * wk[k].x; acc.y += q * wk[k].y;
            acc.z += q * wk[k].z; acc.w += q * wk[k].w;
        }
        atomicAdd(&g_uacc[4 * t + 0], acc.x);
        atomicAdd(&g_uacc[4 * t + 1], acc.y);
        atomicAdd(&g_uacc[4 * t + 2], acc.z);
        atomicAdd(&g_uacc[4 * t + 3], acc.w);
    } else {
        // ===== av for 8 tail rows (blocks 128-143) =====
        int l = ((b - 128) << 3) + wid;
        const float4* xr4 = (const float4*)(x + (size_t)(TT - 1 - l) * CC);
        const float4* wv4 = (const float4*)(W + (size_t)(2 * CC) * CC);
        float4 xa[8], wa[8];
#pragma unroll
        for (int c = 0; c < 8; c++) xa[c] = xr4[c * 32 + lane];
#pragma unroll
        for (int c = 0; c < 8; c++) wa[c] = wv4[c * 32 + lane];
        float s = 0.f;
#pragma unroll
        for (int c = 0; c < 8; c++)
            s += xa[c].x * wa[c].x + xa[c].y * wa[c].y + xa[c].z * wa[c].z + xa[c].w * wa[c].w;
        s = wred_sum(s);
        if (lane == 0) g_av[l] = s;
    }

    // block 0: 2/a table (salpha visible after the syncthreads above)
    if (b == 0 && t < N_ITERS) tia[t] = 2.0f / (salpha + (float)t);

    // C blocks prefetch their x tail rows (independent of u) before the barrier
    float4 xc[8];
    if (b < 16) {
        int l = (b << 3) + wid;
        const float4* xr4 = (const float4*)(x + (size_t)(TT - 1 - l) * CC);
#pragma unroll
        for (int c = 0; c < 8; c++) xc[c] = xr4[c * 32 + lane];
    }
    gbar_arrive(0);
    if (b >= 16) return;                        // 128 blocks done
    gbar_wait(0, GRID);

    // ===== STAGE C (blocks 0-15): tail att ====================================
    ((float4*)sbuf)[t] = ((const float4*)g_uacc)[t];     // u, L2-hot
    __syncthreads();
    {
        int l = (b << 3) + wid;
        const float4* su4 = (const float4*)sbuf;
        float du = 0.f;
#pragma unroll
        for (int c = 0; c < 8; c++) {
            float4 u4 = su4[c * 32 + lane];
            du += xc[c].x * u4.x + xc[c].y * u4.y + xc[c].z * u4.z + xc[c].w * u4.w;
        }
        du = wred_sum(du);
        if (lane == 0) g_att[l] = (l == 0) ? neg_inf() : du * SCALE;
    }
    gbar_arrive(1);
    if (b != 0) return;

    // av prefetch while waiting for the 16 C arrivals
    float v0 = (t < NROWS) ? g_av[t] : 0.f;
    gbar_wait(1, 16);

    // replay-safe resets (only block 0 alive; readers of g_uacc all passed bar1)
    ((float4*)g_uacc)[t] = make_float4(0.f, 0.f, 0.f, 0.f);
    if (t == 0) { g_barc[0] = 0; g_barc[32] = 0; }

    // ===== STAGE D (block 0): stats + serial recurrence =======================
    float a0 = (t < NROWS) ? g_att[t] : neg_inf();

    float lm = a0;
#pragma unroll
    for (int o = 16; o; o >>= 1) lm = fmaxf(lm, __shfl_xor_sync(0xffffffffu, lm, o));
    if (lane == 0) red[wid] = lm;
    __syncthreads();
    if (t == 0) {
        float m0 = red[0];
#pragma unroll
        for (int i = 1; i < 8; i++) m0 = fmaxf(m0, red[i]);
        smax = m0;
    }
    __syncthreads();
    const float m = smax;

    if (t < NROWS) {
        float e0 = __expf(a0 - m);
        float ps = e0, pb = e0 * (float)t, py = e0 * v0;
#pragma unroll
        for (int o = 1; o < 32; o <<= 1) {
            float ts = __shfl_up_sync(0xffffffffu, ps, o);
            float tb = __shfl_up_sync(0xffffffffu, pb, o);
            float ty = __shfl_up_sync(0xffffffffu, py, o);
            if (lane >= o) { ps += ts; pb += tb; py += ty; }
        }
        if (lane == 31) { fs[wid] = ps; fb[wid] = pb; fy[wid] = py; }
        __syncthreads();
        if (t == 0) {
            float cs = 0.f, cb = 0.f, cy = 0.f;
#pragma unroll
            for (int i = 0; i < 4; i++) {
                float ns = fs[i], nb = fb[i], ny = fy[i];
                fs[i] = cs; fb[i] = cb; fy[i] = cy;
                cs += ns; cb += nb; cy += ny;
            }
        }
        __syncthreads();
        ps += fs[wid]; pb += fb[wid]; py += fy[wid];
        sS[t + 1] = ps; sB[t + 1] = pb; sY[t + 1] = py;
        bu_tab[t + 1] = pb / ps;
        if (t == 0) { sS[0] = 0.f; sB[0] = 0.f; sY[0] = 0.f; bu_tab[0] = 0.f; }
    } else {
        __syncthreads(); __syncthreads();
    }
    __syncthreads();

    // serial recurrence: kk = 2 + bb*(2/a);  bb += bu_tab[w]
    float bb = sbeta, k_old = 0.f;
    float s_f = 1.f, ys_f = 0.f;
    for (int it = 0; it < N_ITERS; it++) {
        float kk = fmaf(bb, tia[it], 2.0f);
        int w = __float2int_ru(kk);
        if (w < 1) w = 1;

        float s, bs, ys;
        if (w <= NROWS) {
            s = sS[w]; bs = sB[w]; ys = sY[w];
            bb += bu_tab[w];
        } else {
            if (w > TT) w = TT;
            // exact deep fallback (never taken for these inputs): online softmax
            const float4* u4  = (const float4*)sbuf;     // u lives in smem
            const float4* wv4 = (const float4*)(W + (size_t)(2 * CC) * CC);
            float m_r = neg_inf(), s_r = 0.f, b_r = 0.f, y_r = 0.f;
            for (int l = wid; l < w; l += 8) {
                if (l == 0) continue;                    // masked position
                const float4* xr = (const float4*)(x + (size_t)(TT - 1 - l) * CC);
                float du = 0.f, dv = 0.f;
                for (int c = 0; c < 8; c++) {
                    float4 xa = xr[c * 32 + lane];
                    float4 ub = u4[c * 32 + lane];
                    float4 vb = wv4[c * 32 + lane];
                    du += xa.x * ub.x + xa.y * ub.y + xa.z * ub.z + xa.w * ub.w;
                    dv += xa.x * vb.x + xa.y * vb.y + xa.z * vb.z + xa.w * vb.w;
                }
                du = wred_sum(du); dv = wred_sum(dv);
                float att = du * SCALE;
                float mn = fmaxf(m_r, att);
                float ro = __expf(m_r - mn);
                float e  = __expf(att - mn);
                s_r = s_r * ro + e;
                b_r = b_r * ro + e * (float)l;
                y_r = y_r * ro + e * dv;
                m_r = mn;
            }
            if (lane == 0) { fm[wid] = m_r; fs[wid] = s_r; fb[wid] = b_r; fy[wid] = y_r; }
            __syncthreads();
            float M = fm[0];
            for (int i = 1; i < 8; i++) M = fmaxf(M, fm[i]);
            s = 0.f; bs = 0.f; ys = 0.f;
            for (int i = 0; i < 8; i++) {
                float r2 = __expf(fm[i] - M);
                s  += fs[i] * r2;
                bs += fb[i] * r2;
                ys += fy[i] * r2;
            }
            __syncthreads();
            bb += bs / s;
        }

        s_f = s; ys_f = ys;
        bool stop = (kk > (float)TT) || (kk < k_old);
        k_old = kk;
        if (stop) break;
    }
    if (t == 0) out[0] = ys_f / s_f;
}

// ---------------------------------------------------------------------------
extern "C" void kernel_launch(void* const* d_in, const int* in_sizes, int n_in,
                              void* d_out, int out_size) {
    const float* x = nullptr;
    const float* W = nullptr;
    const float* alpha = nullptr;
    const float* beta = nullptr;
    for (int i = 0; i < n_in; i++) {
        if (in_sizes[i] == TT * CC)                x = (const float*)d_in[i];
        else if (in_sizes[i] == (2 * CC + 1) * CC) W = (const float*)d_in[i];
        else if (in_sizes[i] == 1) {
            if (!alpha) alpha = (const float*)d_in[i];
            else        beta  = (const float*)d_in[i];
        }
    }
    float* out = (float*)d_out;
    k_all<<<GRID, NTH>>>(x, W, alpha, beta, out);
}

// round 11
// speedup vs baseline: 1.2160x; 1.2160x over previous
#include <cuda_runtime.h>
#include <cstdint>

#define TT 16384
#define CC 1024
#define NROWS 128           // tail rows in stats table (window provably < 25)
#define N_ITERS 30
#define GRID 144            // <= 148 SMs -> one wave, safe software grid barrier
#define NTH 256

__device__ float g_up[128 * CC];   // per-block partial u (512 KB)
__device__ float g_u[CC];
__device__ float g_att[NROWS];
__device__ float g_av[NROWS];
__device__ int   g_barc[3 * 32];   // one cache line per phase; left 0 after launch

#define SCALE 3.125e-5f     // 0.001 / sqrt(1024)

__device__ __forceinline__ float neg_inf() { return __int_as_float(0xff800000); }

__device__ __forceinline__ void gbar_arrive(int ph) {
    __syncthreads();
    if (threadIdx.x == 0) {
        __threadfence();
        atomicAdd(&g_barc[ph << 5], 1);
    }
}
__device__ __forceinline__ void gbar_wait(int ph, int count) {
    if (threadIdx.x == 0) {
        while (*(volatile int*)&g_barc[ph << 5] < count) { }
        __threadfence();
    }
    __syncthreads();
}

__device__ __forceinline__ float wred_sum(float v) {
#pragma unroll
    for (int o = 16; o; o >>= 1) v += __shfl_xor_sync(0xffffffffu, v, o);
    return v;
}

__global__ void __launch_bounds__(NTH, 1)
k_all(const float* __restrict__ x, const float* __restrict__ W,
      const float* __restrict__ alpha, const float* __restrict__ beta,
      float* __restrict__ out)
{
    __shared__ float  sq[8];                   // this block's 8 q values
    __shared__ float4 c1red[16][16];           // C1 cross-group reduction
    __shared__ float  sbuf[CC];                // u in stage C2 / D fallback
    __shared__ float  sS[NROWS + 1], sB[NROWS + 1], sY[NROWS + 1];
    __shared__ float  bu_tab[NROWS + 1];
    __shared__ float  tia[32];
    __shared__ float  red[8];
    __shared__ float  fm[8], fs[8], fb[8], fy[8];
    __shared__ float  smax, salpha, sbeta;

    const int b = blockIdx.x, t = threadIdx.x;
    const int lane = t & 31, wid = t >> 5;

    if (b == 0 && t == 0) { salpha = *alpha; sbeta = *beta; }

    // ========= STAGE A+B fused (blocks 0-127): q for 8 rows, then partial u ===
    if (b < 128) {
        const int i0 = b << 3;
        const float* Wk = W + (size_t)CC * CC;

        // coalesced front-batch of this block's 8 full W_k rows
        float4 wk[8];
#pragma unroll
        for (int k = 0; k < 8; k++)
            wk[k] = ((const float4*)(Wk + (size_t)(i0 + k) * CC))[t];

        // q[i0+wid] = x_last . W_q[i0+wid]
        const float4* xl4 = (const float4*)(x + (size_t)(TT - 1) * CC);
        const float4* wr4 = (const float4*)(W + (size_t)(i0 + wid) * CC);
        float4 xa[8], wa[8];
#pragma unroll
        for (int c = 0; c < 8; c++) xa[c] = xl4[c * 32 + lane];
#pragma unroll
        for (int c = 0; c < 8; c++) wa[c] = wr4[c * 32 + lane];
        float s = 0.f;
#pragma unroll
        for (int c = 0; c < 8; c++)
            s += xa[c].x * wa[c].x + xa[c].y * wa[c].y + xa[c].z * wa[c].z + xa[c].w * wa[c].w;
        s = wred_sum(s);
        if (lane == 0) sq[wid] = s;
        __syncthreads();                       // also publishes salpha/sbeta (block 0)

        // partial u over this block's 8 i-rows, all 1024 j (thread t owns j4 = t)
        float4 acc = make_float4(0.f, 0.f, 0.f, 0.f);
#pragma unroll
        for (int k = 0; k < 8; k++) {
            float q = sq[k];
            acc.x += q * wk[k].x; acc.y += q * wk[k].y;
            acc.z += q * wk[k].z; acc.w += q * wk[k].w;
        }
        ((float4*)g_up)[b * 256 + t] = acc;
    } else {
        // av for 8 tail rows (blocks 128-143)
        int l = ((b - 128) << 3) + wid;
        const float4* xr4 = (const float4*)(x + (size_t)(TT - 1 - l) * CC);
        const float4* wv4 = (const float4*)(W + (size_t)(2 * CC) * CC);
        float4 xa[8], wa[8];
#pragma unroll
        for (int c = 0; c < 8; c++) xa[c] = xr4[c * 32 + lane];
#pragma unroll
        for (int c = 0; c < 8; c++) wa[c] = wv4[c * 32 + lane];
        float s = 0.f;
#pragma unroll
        for (int c = 0; c < 8; c++)
            s += xa[c].x * wa[c].x + xa[c].y * wa[c].y + xa[c].z * wa[c].z + xa[c].w * wa[c].w;
        s = wred_sum(s);
        if (lane == 0) g_av[l] = s;
    }

    // block 0: 2/a table while still parallel
    if (b == 0 && t < N_ITERS) tia[t] = 2.0f / (salpha + (float)t);

    gbar_arrive(0);
    if (b >= 16) return;                        // 128 blocks exit; bar1/2 count 16 only
    gbar_wait(0, GRID);

    // ========= STAGE C1 (blocks 0-15): reduce 128 partials -> g_u chunk =======
    {
        const float4* up4 = (const float4*)g_up;
        int col = t & 15;                  // 16 float4 columns per block
        int pg  = t >> 4;                  // 16 partial-groups of 8
        int jf  = (b << 4) + col;
        float4 acc = make_float4(0.f, 0.f, 0.f, 0.f);
#pragma unroll
        for (int p = 0; p < 8; p++) {
            float4 v = up4[(pg * 8 + p) * 256 + jf];
            acc.x += v.x; acc.y += v.y; acc.z += v.z; acc.w += v.w;
        }
        c1red[pg][col] = acc;
        __syncthreads();
        if (t < 16) {
            float4 r = c1red[0][t];
#pragma unroll
            for (int g = 1; g < 16; g++) {
                float4 p = c1red[g][t];
                r.x += p.x; r.y += p.y; r.z += p.z; r.w += p.w;
            }
            ((float4*)g_u)[(b << 4) + t] = r;
        }
    }
    gbar_arrive(1);

    // prefetch x tail rows for C2 (independent of u; overlaps barrier wait)
    float4 xc[8];
    {
        int l = (b << 3) + wid;
        const float4* xr4 = (const float4*)(x + (size_t)(TT - 1 - l) * CC);
#pragma unroll
        for (int c = 0; c < 8; c++) xc[c] = xr4[c * 32 + lane];
    }
    gbar_wait(1, 16);

    // ========= STAGE C2 (blocks 0-15): tail att ===============================
    {
        ((float4*)sbuf)[t] = ((const float4*)g_u)[t];
        __syncthreads();
        int l = (b << 3) + wid;
        const float4* su4 = (const float4*)sbuf;
        float du = 0.f;
#pragma unroll
        for (int c = 0; c < 8; c++) {
            float4 u4 = su4[c * 32 + lane];
            du += xc[c].x * u4.x + xc[c].y * u4.y + xc[c].z * u4.z + xc[c].w * u4.w;
        }
        du = wred_sum(du);
        if (lane == 0) g_att[l] = (l == 0) ? neg_inf() : du * SCALE;
    }
    gbar_arrive(2);
    if (b != 0) return;

    // av prefetch while waiting for the 16 C arrivals
    float v0 = (t < NROWS) ? g_av[t] : 0.f;
    gbar_wait(2, 16);
    if (t == 0) { g_barc[0] = 0; g_barc[32] = 0; g_barc[64] = 0; }   // replay-safe

    // ========= STAGE D (block 0): stats + serial recurrence ===================
    float a0 = (t < NROWS) ? g_att[t] : neg_inf();

    float lm = a0;
#pragma unroll
    for (int o = 16; o; o >>= 1) lm = fmaxf(lm, __shfl_xor_sync(0xffffffffu, lm, o));
    if (lane == 0) red[wid] = lm;
    __syncthreads();
    if (t == 0) {
        float m0 = red[0];
#pragma unroll
        for (int i = 1; i < 8; i++) m0 = fmaxf(m0, red[i]);
        smax = m0;
    }
    __syncthreads();
    const float m = smax;

    if (t < NROWS) {
        float e0 = __expf(a0 - m);
        float ps = e0, pb = e0 * (float)t, py = e0 * v0;
#pragma unroll
        for (int o = 1; o < 32; o <<= 1) {
            float ts = __shfl_up_sync(0xffffffffu, ps, o);
            float tb = __shfl_up_sync(0xffffffffu, pb, o);
            float ty = __shfl_up_sync(0xffffffffu, py, o);
            if (lane >= o) { ps += ts; pb += tb; py += ty; }
        }
        if (lane == 31) { fs[wid] = ps; fb[wid] = pb; fy[wid] = py; }
        __syncthreads();
        if (t == 0) {
            float cs = 0.f, cb = 0.f, cy = 0.f;
#pragma unroll
            for (int i = 0; i < 4; i++) {
                float ns = fs[i], nb = fb[i], ny = fy[i];
                fs[i] = cs; fb[i] = cb; fy[i] = cy;
                cs += ns; cb += nb; cy += ny;
            }
        }
        __syncthreads();
        ps += fs[wid]; pb += fb[wid]; py += fy[wid];
        sS[t + 1] = ps; sB[t + 1] = pb; sY[t + 1] = py;
        bu_tab[t + 1] = pb / ps;
        if (t == 0) { sS[0] = 0.f; sB[0] = 0.f; sY[0] = 0.f; bu_tab[0] = 0.f; }
    } else {
        __syncthreads(); __syncthreads();
    }
    __syncthreads();

    // serial recurrence: kk = 2 + bb*(2/a);  bb += bu_tab[w]
    float bb = sbeta, k_old = 0.f;
    float s_f = 1.f, ys_f = 0.f;
    for (int it = 0; it < N_ITERS; it++) {
        float kk = fmaf(bb, tia[it], 2.0f);
        int w = __float2int_ru(kk);
        if (w < 1) w = 1;

        float s, bs, ys;
        if (w <= NROWS) {
            s = sS[w]; bs = sB[w]; ys = sY[w];
            bb += bu_tab[w];
        } else {
            if (w > TT) w = TT;
            // exact deep fallback (never taken for these inputs): online softmax
            const float4* u4  = (const float4*)sbuf;     // u lives in smem
            const float4* wv4 = (const float4*)(W + (size_t)(2 * CC) * CC);
            float m_r = neg_inf(), s_r = 0.f, b_r = 0.f, y_r = 0.f;
            for (int l = wid; l < w; l += 8) {
                if (l == 0) continue;                    // masked position
                const float4* xr = (const float4*)(x + (size_t)(TT - 1 - l) * CC);
                float du = 0.f, dv = 0.f;
                for (int c = 0; c < 8; c++) {
                    float4 xa = xr[c * 32 + lane];
                    float4 ub = u4[c * 32 + lane];
                    float4 vb = wv4[c * 32 + lane];
                    du += xa.x * ub.x + xa.y * ub.y + xa.z * ub.z + xa.w * ub.w;
                    dv += xa.x * vb.x + xa.y * vb.y + xa.z * vb.z + xa.w * vb.w;
                }
                du = wred_sum(du); dv = wred_sum(dv);
                float att = du * SCALE;
                float mn = fmaxf(m_r, att);
                float ro = __expf(m_r - mn);
                float e  = __expf(att - mn);
                s_r = s_r * ro + e;
                b_r = b_r * ro + e * (float)l;
                y_r = y_r * ro + e * dv;
                m_r = mn;
            }
            if (lane == 0) { fm[wid] = m_r; fs[wid] = s_r; fb[wid] = b_r; fy[wid] = y_r; }
            __syncthreads();
            float M = fm[0];
            for (int i = 1; i < 8; i++) M = fmaxf(M, fm[i]);
            s = 0.f; bs = 0.f; ys = 0.f;
            for (int i = 0; i < 8; i++) {
                float r2 = __expf(fm[i] - M);
                s  += fs[i] * r2;
                bs += fb[i] * r2;
                ys += fy[i] * r2;
            }
            __syncthreads();
            bb += bs / s;
        }

        s_f = s; ys_f = ys;
        bool stop = (kk > (float)TT) || (kk < k_old);
        k_old = kk;
        if (stop) break;
    }
    if (t == 0) out[0] = ys_f / s_f;
}

// ---------------------------------------------------------------------------
extern "C" void kernel_launch(void* const* d_in, const int* in_sizes, int n_in,
                              void* d_out, int out_size) {
    const float* x = nullptr;
    const float* W = nullptr;
    const float* alpha = nullptr;
    const float* beta = nullptr;
    for (int i = 0; i < n_in; i++) {
        if (in_sizes[i] == TT * CC)                x = (const float*)d_in[i];
        else if (in_sizes[i] == (2 * CC + 1) * CC) W = (const float*)d_in[i];
        else if (in_sizes[i] == 1) {
            if (!alpha) alpha = (const float*)d_in[i];
            else        beta  = (const float*)d_in[i];
        }
    }
    float* out = (float*)d_out;
    k_all<<<GRID, NTH>>>(x, W, alpha, beta, out);
}